// round 16
// baseline (speedup 1.0000x reference)
#include <cuda_runtime.h>
#include <cstdint>

typedef unsigned long long u64;

// fp32 scratch for W_h powers + pre-split bf16 B matrices (device globals)
__device__ float g_W2[65536];
__device__ float g_W4[65536];
__device__ float g_W8[65536];
__device__ float g_W16[65536];
__device__ float g_W32[65536];
// bf16 hi/lo packed k-pairs: matrices 0:Wx 1:Wh 2:W2 3:W4 4:W8 5:W16
__device__ uint32_t g_Bh16[6 * 32768];
__device__ uint32_t g_Bl16[6 * 32768];

// ---------------- f32x2 packed helpers (scan path) ---------------------------
__device__ __forceinline__ u64 ffma2(u64 a, u64 b, u64 c) {
    u64 d;
    asm("fma.rn.f32x2 %0, %1, %2, %3;" : "=l"(d) : "l"(a), "l"(b), "l"(c));
    return d;
}
__device__ __forceinline__ float2 unpack2(u64 v) {
    float2 f;
    asm("mov.b64 {%0, %1}, %2;" : "=f"(f.x), "=f"(f.y) : "l"(v));
    return f;
}
// pack two fp32 -> bf16x2 (x0 in low half = even k)
__device__ __forceinline__ uint32_t packbf(float x0, float x1) {
    uint32_t r;
    asm("cvt.rn.bf16x2.f32 %0, %1, %2;" : "=r"(r) : "f"(x1), "f"(x0));
    return r;
}

// mma.sync m16n8k16 bf16 (baseline PTX, sm_80+)
#define MMA_BF16(d, a, b0, b1)                                             \
    asm volatile(                                                          \
        "mma.sync.aligned.m16n8k16.row.col.f32.bf16.bf16.f32 "             \
        "{%0,%1,%2,%3}, {%4,%5,%6,%7}, {%8,%9}, {%0,%1,%2,%3};"            \
        : "+f"((d)[0]), "+f"((d)[1]), "+f"((d)[2]), "+f"((d)[3])           \
        : "r"((a)[0]), "r"((a)[1]), "r"((a)[2]), "r"((a)[3]),              \
          "r"(b0), "r"(b1))

// SMEM u32 offsets:
//   B tile: 128 rows x 132 u32 (4-pad -> banks 4g+c all distinct), hi + lo
//   A tile: per-pair private, double-buffered; 32 rows x 12 u32 per half
#define SMB_HI 0
#define SMB_LO 16896
#define SMA(p, b, h) (33792 + ((((p) * 2 + (b)) * 2 + (h)) * 384))
static constexpr int MMA_SMEM_BYTES = 39936 * 4;   // 159744

// =============================================================================
// Unified tensor-core bf16 3-pass GEMM, B-resident, pair-synced.
//   mode 0 (xproj):   out[rr,:]  = X[rr,:] @ Wx^T + bias          (overwrite)
//   mode 1 (corr l):  out[b,t]  += W^(2^(l-1)) @ out[b, t-2^(l-1)]
//   mode 2 (bkfl l):  out[b,t]  += W^(2^l)     @ h[b, t-2^l] (i==0 -> hidden)
// CTA 128(M) x 128(N) x K=256; 16 chunks of 16.  8 warps; pair p = wid&3 owns
// M-rows p*32..+31; member = wid>>2 picks N-half.  Warp tile 32x64.
// =============================================================================
__global__ __launch_bounds__(256) void mma_gemm(
    const float* __restrict__ X, const float* __restrict__ hidden,
    const float* __restrict__ W, const float* __restrict__ bias,
    float* __restrict__ out, int mode, int level)
{
    extern __shared__ uint32_t smu[];
    const int tid  = threadIdx.x;
    const int lane = tid & 31, wid = tid >> 5;
    const int pair = wid & 3, mem = wid >> 2;
    const int mBase = blockIdx.x * 128, nBase = blockIdx.y * 128;

    // ---- B prologue: copy pre-split bf16 tile (rows nBase..+127) into SMEM ----
    const int matIdx = (mode == 0) ? 0 : ((mode == 1) ? level : level + 1);
    {
        const uint32_t* gh = g_Bh16 + matIdx * 32768 + nBase * 128;
        const uint32_t* gl = g_Bl16 + matIdx * 32768 + nBase * 128;
        #pragma unroll 4
        for (int idx = tid; idx < 16384; idx += 256) {
            const int r = idx >> 7, ku = idx & 127;
            smu[SMB_HI + r * 132 + ku] = gh[idx];
            smu[SMB_LO + r * 132 + ku] = gl[idx];
        }
    }

    // ---- A row for staging: this thread stages row (pair*32 + lane), k-half mem ----
    const int arow = pair * 32 + lane;
    const int rA   = mBase + arow;
    const float* Aptr;
    if (mode == 0) {
        Aptr = X + (size_t)rA * 256;
    } else {
        const int l2 = (mode == 1) ? (11 - level) : (10 - level);
        const int b = rA >> l2, i = rA & ((1 << l2) - 1);
        int s;
        if (mode == 1) s = ((i << level) + (1 << level) - 1) - (1 << (level - 1));
        else           s = ((i << (level + 1)) + (1 << level) - 1) - (1 << level);
        Aptr = (mode == 2 && i == 0) ? hidden + (size_t)b * 256
                                     : out + ((size_t)b * 2048 + s) * 256;
    }

    float4 fa0, fa1;
    auto fetch = [&](int kt) {
        const float* ap = Aptr + kt * 16 + mem * 8;
        fa0 = *(const float4*)(ap);
        fa1 = *(const float4*)(ap + 4);
    };
    auto split2 = [&](float x0, float x1, uint32_t& hi, uint32_t& lo) {
        hi = packbf(x0, x1);
        float r0 = x0 - __uint_as_float(hi << 16);
        float r1 = x1 - __uint_as_float(hi & 0xffff0000u);
        lo = packbf(r0, r1);
    };
    auto stage = [&](int buf) {
        uint32_t h[4], l[4];
        split2(fa0.x, fa0.y, h[0], l[0]);
        split2(fa0.z, fa0.w, h[1], l[1]);
        split2(fa1.x, fa1.y, h[2], l[2]);
        split2(fa1.z, fa1.w, h[3], l[3]);
        const int o = lane * 12 + mem * 4;
        *(uint4*)(smu + SMA(pair, buf, 0) + o) = make_uint4(h[0], h[1], h[2], h[3]);
        *(uint4*)(smu + SMA(pair, buf, 1) + o) = make_uint4(l[0], l[1], l[2], l[3]);
    };

    // ---- accumulators ----
    float acc[2][8][4];
    #pragma unroll
    for (int tm = 0; tm < 2; tm++)
        #pragma unroll
        for (int tn = 0; tn < 8; tn++)
            #pragma unroll
            for (int q = 0; q < 4; q++) acc[tm][tn][q] = 0.f;

    const int wm = pair * 32;
    const int wn = mem * 64;
    const int g  = lane >> 2;
    const int c  = lane & 3;

    fetch(0);
    stage(0);
    __syncthreads();      // B tile + A chunk 0 visible

    #pragma unroll 1
    for (int kt = 0; kt < 16; kt++) {
        const int cur = kt & 1;
        if (kt < 15) fetch(kt + 1);

        const uint32_t* Ah = smu + SMA(pair, cur, 0);
        const uint32_t* Al = smu + SMA(pair, cur, 1);
        uint32_t ah[2][4], al[2][4];
        #pragma unroll
        for (int tm = 0; tm < 2; tm++) {
            const int o0 = (tm * 16 + g) * 12 + c;
            const int o1 = o0 + 96;                        // row +8
            ah[tm][0] = Ah[o0];     ah[tm][1] = Ah[o1];
            ah[tm][2] = Ah[o0 + 4]; ah[tm][3] = Ah[o1 + 4];
            al[tm][0] = Al[o0];     al[tm][1] = Al[o1];
            al[tm][2] = Al[o0 + 4]; al[tm][3] = Al[o1 + 4];
        }
        #pragma unroll
        for (int tn = 0; tn < 8; tn++) {
            const int ob = (wn + tn * 8 + g) * 132 + kt * 8 + c;
            uint32_t bh0 = smu[SMB_HI + ob], bh1 = smu[SMB_HI + ob + 4];
            uint32_t bl0 = smu[SMB_LO + ob], bl1 = smu[SMB_LO + ob + 4];
            MMA_BF16(acc[0][tn], ah[0], bh0, bh1);
            MMA_BF16(acc[1][tn], ah[1], bh0, bh1);
            MMA_BF16(acc[0][tn], ah[0], bl0, bl1);
            MMA_BF16(acc[1][tn], ah[1], bl0, bl1);
            MMA_BF16(acc[0][tn], al[0], bh0, bh1);
            MMA_BF16(acc[1][tn], al[1], bh0, bh1);
        }
        if (kt < 15) stage(cur ^ 1);
        // pair-scoped barrier (warps wid and wid+4; drains STS)
        asm volatile("bar.sync %0, %1;" :: "r"(pair + 1), "r"(64) : "memory");
    }

    // ---- epilogue (m16n8 D mapping: rows g/g+8, cols 2c/2c+1; proven) ----
    auto row_ptr = [&](int rr) -> float* {
        if (mode == 0) return out + (size_t)rr * 256;
        const int l2 = (mode == 1) ? (11 - level) : (10 - level);
        const int b = rr >> l2, i = rr & ((1 << l2) - 1);
        const int t = (mode == 1) ? ((i << level) + (1 << level) - 1)
                                  : ((i << (level + 1)) + (1 << level) - 1);
        return out + ((size_t)b * 2048 + t) * 256;
    };

    #pragma unroll
    for (int tm = 0; tm < 2; tm++) {
        const int rr0 = mBase + wm + tm * 16 + g;
        float* o0 = row_ptr(rr0);
        float* o1 = row_ptr(rr0 + 8);
        #pragma unroll
        for (int tn = 0; tn < 8; tn++) {
            const int col = nBase + wn + tn * 8 + 2 * c;
            if (mode == 0) {
                float2 bv = *(const float2*)(bias + col);
                float2 v0 = make_float2(acc[tm][tn][0] + bv.x, acc[tm][tn][1] + bv.y);
                float2 v1 = make_float2(acc[tm][tn][2] + bv.x, acc[tm][tn][3] + bv.y);
                *(float2*)(o0 + col) = v0;
                *(float2*)(o1 + col) = v1;
            } else {
                float2 e0 = *(const float2*)(o0 + col);
                float2 e1 = *(const float2*)(o1 + col);
                e0.x += acc[tm][tn][0]; e0.y += acc[tm][tn][1];
                e1.x += acc[tm][tn][2]; e1.y += acc[tm][tn][3];
                *(float2*)(o0 + col) = e0;
                *(float2*)(o1 + col) = e1;
            }
        }
    }
}

// =============================================================================
// Matrix power kernels (4 output rows per block) + bf16 split prepass.
// =============================================================================
__global__ __launch_bounds__(256) void w2_kernel(const float* __restrict__ W)
{
    __shared__ float rowj[4][256];
    const int j0 = blockIdx.x * 4, k = threadIdx.x;
    #pragma unroll
    for (int r = 0; r < 4; r++)
        rowj[r][k] = W[(size_t)(j0 + r) * 512 + 256 + k];
    __syncthreads();
    float a0 = 0.f, a1 = 0.f, a2 = 0.f, a3 = 0.f;
    #pragma unroll 8
    for (int m = 0; m < 256; m++) {
        float s = W[(size_t)m * 512 + 256 + k];
        a0 += rowj[0][m] * s; a1 += rowj[1][m] * s;
        a2 += rowj[2][m] * s; a3 += rowj[3][m] * s;
    }
    g_W2[(j0 + 0) * 256 + k] = a0; g_W2[(j0 + 1) * 256 + k] = a1;
    g_W2[(j0 + 2) * 256 + k] = a2; g_W2[(j0 + 3) * 256 + k] = a3;
}

__global__ __launch_bounds__(256) void wsq_kernel(int which)
{
    const float* src = (which == 0) ? g_W2 : (which == 1) ? g_W4
                     : (which == 2) ? g_W8 : g_W16;
    float*       dst = (which == 0) ? g_W4 : (which == 1) ? g_W8
                     : (which == 2) ? g_W16 : g_W32;
    __shared__ float rowj[4][256];
    const int j0 = blockIdx.x * 4, k = threadIdx.x;
    #pragma unroll
    for (int r = 0; r < 4; r++)
        rowj[r][k] = src[(j0 + r) * 256 + k];
    __syncthreads();
    float a0 = 0.f, a1 = 0.f, a2 = 0.f, a3 = 0.f;
    #pragma unroll 8
    for (int m = 0; m < 256; m++) {
        float s = src[m * 256 + k];
        a0 += rowj[0][m] * s; a1 += rowj[1][m] * s;
        a2 += rowj[2][m] * s; a3 += rowj[3][m] * s;
    }
    dst[(j0 + 0) * 256 + k] = a0; dst[(j0 + 1) * 256 + k] = a1;
    dst[(j0 + 2) * 256 + k] = a2; dst[(j0 + 3) * 256 + k] = a3;
}

__global__ __launch_bounds__(128) void bsplit_kernel(const float* __restrict__ W)
{
    const int m = blockIdx.y, j = blockIdx.x, t = threadIdx.x;
    float x0, x1;
    if (m == 0)      { x0 = W[(size_t)j * 512 + 2 * t];       x1 = W[(size_t)j * 512 + 2 * t + 1]; }
    else if (m == 1) { x0 = W[(size_t)j * 512 + 256 + 2 * t]; x1 = W[(size_t)j * 512 + 257 + 2 * t]; }
    else {
        const float* S = (m == 2) ? g_W2 : (m == 3) ? g_W4 : (m == 4) ? g_W8 : g_W16;
        x0 = S[j * 256 + 2 * t]; x1 = S[j * 256 + 2 * t + 1];
    }
    uint32_t hi = packbf(x0, x1);
    float r0 = x0 - __uint_as_float(hi << 16);
    float r1 = x1 - __uint_as_float(hi & 0xffff0000u);
    uint32_t lo = packbf(r0, r1);
    g_Bh16[m * 32768 + j * 128 + t] = hi;
    g_Bl16[m * 32768 + j * 128 + t] = lo;
}

// =============================================================================
// Phase 2: W^32 scan, 64 steps (fp32 FFMA2 path; rows ≡31 mod 32).
// =============================================================================
__global__ __launch_bounds__(512, 1) void rnn_scan(
    const float* __restrict__ hidden, float* __restrict__ out)
{
    extern __shared__ u64 dynsm[];
    u64*   resw = dynsm;                     // [20][512] u64         (81920 B)
    float* part = (float*)(dynsm + 10240);   // [256*9] floats         (9216 B)
    u64*   h2   = dynsm + 11392;             // [2][8*17] u64 (padded) (2176 B)

    const int tid  = threadIdx.x;
    const int b    = blockIdx.x;
    const int q    = tid & 7;
    const int jset = tid >> 3;

    u64 w[4][11];
    #pragma unroll
    for (int u = 0; u < 4; u++) {
        const u64* wr = (const u64*)(g_W32 + (size_t)(jset * 4 + u) * 256);
        #pragma unroll
        for (int i = 0; i < 11; i++) w[u][i] = wr[q * 16 + i];
        #pragma unroll
        for (int ir = 0; ir < 5; ir++)
            resw[(u * 5 + ir) * 512 + tid] = wr[q * 16 + 11 + ir];
    }

    if (tid < 128) {
        u64 hv = ((const u64*)(hidden + (size_t)b * 256))[tid];
        h2[(tid >> 4) * 17 + (tid & 15)] = hv;
    }

    float xpre = 0.f;
    float* outp = out + (size_t)b * 2048 * 256 + 31 * 256 + tid;
    if (tid < 256) xpre = *outp;

    __syncthreads();

    const u64* rw = resw + tid;

    #pragma unroll 1
    for (int t = 0; t < 64; t++) {
        const u64* hb = h2 + (t & 1) * 136 + q * 17;
        u64 a0 = 0, a1 = 0, a2 = 0, a3 = 0;
        #pragma unroll
        for (int i = 0; i < 11; i++) {
            u64 hh = hb[i];
            a0 = ffma2(w[0][i], hh, a0);
            a1 = ffma2(w[1][i], hh, a1);
            a2 = ffma2(w[2][i], hh, a2);
            a3 = ffma2(w[3][i], hh, a3);
        }
        #pragma unroll
        for (int ir = 0; ir < 5; ir++) {
            u64 hh = hb[11 + ir];
            a0 = ffma2(rw[(0 * 5 + ir) * 512], hh, a0);
            a1 = ffma2(rw[(1 * 5 + ir) * 512], hh, a1);
            a2 = ffma2(rw[(2 * 5 + ir) * 512], hh, a2);
            a3 = ffma2(rw[(3 * 5 + ir) * 512], hh, a3);
        }
        float2 f0 = unpack2(a0), f1 = unpack2(a1), f2 = unpack2(a2), f3 = unpack2(a3);
        const int pb = (jset * 4) * 9 + q;
        part[pb]      = f0.x + f0.y;
        part[pb + 9]  = f1.x + f1.y;
        part[pb + 18] = f2.x + f2.y;
        part[pb + 27] = f3.x + f3.y;
        __syncthreads();
        if (tid < 256) {
            const float* pr = part + tid * 9;
            float s = ((pr[0] + pr[1]) + (pr[2] + pr[3]))
                    + ((pr[4] + pr[5]) + (pr[6] + pr[7]));
            float hnew = s + xpre;
            int p = tid >> 1;
            float* hw = (float*)(h2 + ((t + 1) & 1) * 136);
            hw[((p >> 4) * 17 + (p & 15)) * 2 + (tid & 1)] = hnew;
            *outp = hnew;                       // h_{32t+31}
            if (t < 63) xpre = outp[8192];      // prefetch c_{32(t+1)+31}
            outp += 8192;
        }
        __syncthreads();
    }
}

// =============================================================================
extern "C" void kernel_launch(void* const* d_in, const int* in_sizes, int n_in,
                              void* d_out, int out_size)
{
    (void)in_sizes; (void)n_in; (void)out_size;
    const float* X      = (const float*)d_in[0];   // input_seq [64,2048,256]
    const float* hidden = (const float*)d_in[1];   // [64,256]
    const float* W      = (const float*)d_in[2];   // [256,512]
    const float* bias   = (const float*)d_in[3];   // [256]
    float* out          = (float*)d_out;           // [64,2048,256]

    cudaFuncSetAttribute(mma_gemm,
        cudaFuncAttributeMaxDynamicSharedMemorySize, MMA_SMEM_BYTES);
    cudaFuncSetAttribute(rnn_scan,
        cudaFuncAttributeMaxDynamicSharedMemorySize, 93312);

    // 1) Wh powers: W2..W32; then bf16 hi/lo pre-split of the 6 B matrices.
    w2_kernel<<<64, 256>>>(W);
    wsq_kernel<<<64, 256>>>(0);
    wsq_kernel<<<64, 256>>>(1);
    wsq_kernel<<<64, 256>>>(2);
    wsq_kernel<<<64, 256>>>(3);
    bsplit_kernel<<<dim3(256, 6), 128>>>(W);

    // 2) xproj (tensor cores): out = X @ Wx^T + bias.
    mma_gemm<<<dim3(1024, 2), 256, MMA_SMEM_BYTES>>>(X, hidden, W, bias, out, 0, 0);

    // 3) correction tree, levels 1..5 (B = Wh, W2, W4, W8, W16).
    mma_gemm<<<dim3(512, 2), 256, MMA_SMEM_BYTES>>>(X, hidden, W, bias, out, 1, 1);
    mma_gemm<<<dim3(256, 2), 256, MMA_SMEM_BYTES>>>(X, hidden, W, bias, out, 1, 2);
    mma_gemm<<<dim3(128, 2), 256, MMA_SMEM_BYTES>>>(X, hidden, W, bias, out, 1, 3);
    mma_gemm<<<dim3(64,  2), 256, MMA_SMEM_BYTES>>>(X, hidden, W, bias, out, 1, 4);
    mma_gemm<<<dim3(32,  2), 256, MMA_SMEM_BYTES>>>(X, hidden, W, bias, out, 1, 5);

    // 4) W^32 scan, 64 steps -> rows 32i+31 become h.
    rnn_scan<<<64, 512, 93312>>>(hidden, out);

    // 5) backfill levels 4..0 (B = W16, W8, W4, W2, Wh).
    mma_gemm<<<dim3(32,  2), 256, MMA_SMEM_BYTES>>>(X, hidden, W, bias, out, 2, 4);
    mma_gemm<<<dim3(64,  2), 256, MMA_SMEM_BYTES>>>(X, hidden, W, bias, out, 2, 3);
    mma_gemm<<<dim3(128, 2), 256, MMA_SMEM_BYTES>>>(X, hidden, W, bias, out, 2, 2);
    mma_gemm<<<dim3(256, 2), 256, MMA_SMEM_BYTES>>>(X, hidden, W, bias, out, 2, 1);
    mma_gemm<<<dim3(512, 2), 256, MMA_SMEM_BYTES>>>(X, hidden, W, bias, out, 2, 0);
}

// round 17
// speedup vs baseline: 1.1825x; 1.1825x over previous
#include <cuda_runtime.h>
#include <cstdint>

typedef unsigned long long u64;

// fp32 scratch for W_h powers (device-global: allocation-free scratch)
__device__ float g_W2[65536];
__device__ float g_W4[65536];
__device__ float g_W8[65536];
__device__ float g_W16[65536];
// pre-split bf16 hi/lo packed k-pairs: 0:Wx 1:Wh 2:W2 3:W4 4:W8
__device__ uint32_t g_Bh16[5 * 32768];
__device__ uint32_t g_Bl16[5 * 32768];

// ---------------- f32x2 packed helpers (scan path) ---------------------------
__device__ __forceinline__ u64 ffma2(u64 a, u64 b, u64 c) {
    u64 d;
    asm("fma.rn.f32x2 %0, %1, %2, %3;" : "=l"(d) : "l"(a), "l"(b), "l"(c));
    return d;
}
__device__ __forceinline__ float2 unpack2(u64 v) {
    float2 f;
    asm("mov.b64 {%0, %1}, %2;" : "=f"(f.x), "=f"(f.y) : "l"(v));
    return f;
}
// pack two fp32 -> bf16x2 (x0 in low half = even k)
__device__ __forceinline__ uint32_t packbf(float x0, float x1) {
    uint32_t r;
    asm("cvt.rn.bf16x2.f32 %0, %1, %2;" : "=r"(r) : "f"(x1), "f"(x0));
    return r;
}

// mma.sync m16n8k16 bf16 (baseline PTX, sm_80+)
#define MMA_BF16(d, a, b0, b1)                                             \
    asm volatile(                                                          \
        "mma.sync.aligned.m16n8k16.row.col.f32.bf16.bf16.f32 "             \
        "{%0,%1,%2,%3}, {%4,%5,%6,%7}, {%8,%9}, {%0,%1,%2,%3};"            \
        : "+f"((d)[0]), "+f"((d)[1]), "+f"((d)[2]), "+f"((d)[3])           \
        : "r"((a)[0]), "r"((a)[1]), "r"((a)[2]), "r"((a)[3]),              \
          "r"(b0), "r"(b1))

// SMEM u32-offsets (identical to the 998us baseline: [row][k-pairs], stride 12)
#define SM_AHI 0
#define SM_ALO 3072
#define SM_BHI 6144
#define SM_BLO 9216
static constexpr int MMA_SMEM_BYTES = 12288 * 4;   // 49152

// =============================================================================
// Unified tensor-core bf16 3-pass GEMM (998us baseline + pre-split B loads).
//   mode 0 (xproj):     out[rr,:]  = X[rr,:] @ Wx^T + bias        (overwrite)
//   mode 1 (corr l):    out[b,t]  += W^(2^(l-1)) @ out[b, t-2^(l-1)]
//   mode 2 (bkfl l):    out[b,t]  += W^(2^l)     @ h[b, t-2^l] (i==0 -> hidden)
// CTA: 128(M) x 128(N) x K=256, 16 double-buffered k-chunks of 16.
// 8 warps, warp tile 32x64 (2x8 m16n8 tiles), passes hi*hi + hi*lo + lo*hi.
// =============================================================================
__global__ __launch_bounds__(256) void mma_gemm(
    const float* __restrict__ X, const float* __restrict__ hidden,
    const float* __restrict__ W, const float* __restrict__ bias,
    float* __restrict__ out, int mode, int level)
{
    extern __shared__ uint32_t smu[];
    const int tid  = threadIdx.x;
    const int lane = tid & 31, wid = tid >> 5;
    const int mBase = blockIdx.x * 128, nBase = blockIdx.y * 128;
    const int lrow = tid & 127, lkg0 = tid >> 7;

    // ---- A global row pointer (proven formulas) ----
    const int rA = mBase + lrow;
    const float* Aptr;
    if (mode == 0) {
        Aptr = X + (size_t)rA * 256;
    } else {
        const int l2 = (mode == 1) ? (11 - level) : (10 - level);
        const int b = rA >> l2, i = rA & ((1 << l2) - 1);
        int s;
        if (mode == 1) s = ((i << level) + (1 << level) - 1) - (1 << (level - 1));
        else           s = ((i << (level + 1)) + (1 << level) - 1) - (1 << level);
        Aptr = (mode == 2 && i == 0) ? hidden + (size_t)b * 256
                                     : out + ((size_t)b * 2048 + s) * 256;
    }

    // ---- pre-split B row pointers (mat 0:Wx 1:Wh 2:W2 3:W4 4:W8) ----
    const int matIdx = (mode == 0) ? 0 : ((mode == 1) ? level : level + 1);
    const uint32_t* BHp = g_Bh16 + matIdx * 32768 + (size_t)(nBase + lrow) * 128 + lkg0 * 4;
    const uint32_t* BLp = g_Bl16 + matIdx * 32768 + (size_t)(nBase + lrow) * 128 + lkg0 * 4;

    // ---- loaders: thread covers 8 contiguous k (lkg0 selects half) ----
    float4 fa0, fa1;
    uint4 fbh, fbl;
    auto fetch = [&](int kt) {
        const float* ap = Aptr + kt * 16 + lkg0 * 8;
        fa0 = *(const float4*)(ap);
        fa1 = *(const float4*)(ap + 4);
        fbh = *(const uint4*)(BHp + kt * 8);
        fbl = *(const uint4*)(BLp + kt * 8);
    };
    auto split2 = [&](float x0, float x1, uint32_t& hi, uint32_t& lo) {
        hi = packbf(x0, x1);
        float r0 = x0 - __uint_as_float(hi << 16);
        float r1 = x1 - __uint_as_float(hi & 0xffff0000u);
        lo = packbf(r0, r1);
    };
    auto stage = [&](int buf) {
        const int base = lrow * 12 + lkg0 * 4 + buf * 1536;
        uint32_t h[4], l[4];
        split2(fa0.x, fa0.y, h[0], l[0]);
        split2(fa0.z, fa0.w, h[1], l[1]);
        split2(fa1.x, fa1.y, h[2], l[2]);
        split2(fa1.z, fa1.w, h[3], l[3]);
        *(uint4*)(smu + SM_AHI + base) = make_uint4(h[0], h[1], h[2], h[3]);
        *(uint4*)(smu + SM_ALO + base) = make_uint4(l[0], l[1], l[2], l[3]);
        *(uint4*)(smu + SM_BHI + base) = fbh;
        *(uint4*)(smu + SM_BLO + base) = fbl;
    };

    // ---- accumulators ----
    float acc[2][8][4];
    #pragma unroll
    for (int tm = 0; tm < 2; tm++)
        #pragma unroll
        for (int tn = 0; tn < 8; tn++)
            #pragma unroll
            for (int q = 0; q < 4; q++) acc[tm][tn][q] = 0.f;

    const int wm = (wid & 3) * 32;
    const int wn = (wid >> 2) * 64;
    const int g  = lane >> 2;
    const int c  = lane & 3;

    fetch(0);
    stage(0);
    __syncthreads();

    #pragma unroll 1
    for (int kt = 0; kt < 16; kt++) {
        const int cur = kt & 1;
        if (kt < 15) fetch(kt + 1);

        const uint32_t* Ah = smu + SM_AHI + cur * 1536;
        const uint32_t* Al = smu + SM_ALO + cur * 1536;
        const uint32_t* Bh = smu + SM_BHI + cur * 1536;
        const uint32_t* Bl = smu + SM_BLO + cur * 1536;

        uint32_t ah[2][4], al[2][4];
        #pragma unroll
        for (int tm = 0; tm < 2; tm++) {
            const int o0 = (wm + tm * 16 + g) * 12 + c;
            const int o1 = o0 + 96;                      // row +8
            ah[tm][0] = Ah[o0];     ah[tm][1] = Ah[o1];
            ah[tm][2] = Ah[o0 + 4]; ah[tm][3] = Ah[o1 + 4];
            al[tm][0] = Al[o0];     al[tm][1] = Al[o1];
            al[tm][2] = Al[o0 + 4]; al[tm][3] = Al[o1 + 4];
        }
        #pragma unroll
        for (int tn = 0; tn < 8; tn++) {
            const int ob = (wn + tn * 8 + g) * 12 + c;
            uint32_t bh0 = Bh[ob], bh1 = Bh[ob + 4];
            uint32_t bl0 = Bl[ob], bl1 = Bl[ob + 4];
            MMA_BF16(acc[0][tn], ah[0], bh0, bh1);
            MMA_BF16(acc[1][tn], ah[1], bh0, bh1);
            MMA_BF16(acc[0][tn], ah[0], bl0, bl1);
            MMA_BF16(acc[1][tn], ah[1], bl0, bl1);
            MMA_BF16(acc[0][tn], al[0], bh0, bh1);
            MMA_BF16(acc[1][tn], al[1], bh0, bh1);
        }
        if (kt < 15) stage(cur ^ 1);
        __syncthreads();
    }

    // ---- epilogue (m16n8 D mapping: rows g/g+8, cols 2c/2c+1; proven) ----
    auto row_ptr = [&](int rr) -> float* {
        if (mode == 0) return out + (size_t)rr * 256;
        const int l2 = (mode == 1) ? (11 - level) : (10 - level);
        const int b = rr >> l2, i = rr & ((1 << l2) - 1);
        const int t = (mode == 1) ? ((i << level) + (1 << level) - 1)
                                  : ((i << (level + 1)) + (1 << level) - 1);
        return out + ((size_t)b * 2048 + t) * 256;
    };

    #pragma unroll
    for (int tm = 0; tm < 2; tm++) {
        const int rr0 = mBase + wm + tm * 16 + g;
        float* o0 = row_ptr(rr0);
        float* o1 = row_ptr(rr0 + 8);
        #pragma unroll
        for (int tn = 0; tn < 8; tn++) {
            const int col = nBase + wn + tn * 8 + 2 * c;
            if (mode == 0) {
                float2 bv = *(const float2*)(bias + col);
                float2 v0 = make_float2(acc[tm][tn][0] + bv.x, acc[tm][tn][1] + bv.y);
                float2 v1 = make_float2(acc[tm][tn][2] + bv.x, acc[tm][tn][3] + bv.y);
                *(float2*)(o0 + col) = v0;
                *(float2*)(o1 + col) = v1;
            } else {
                float2 e0 = *(const float2*)(o0 + col);
                float2 e1 = *(const float2*)(o1 + col);
                e0.x += acc[tm][tn][0]; e0.y += acc[tm][tn][1];
                e1.x += acc[tm][tn][2]; e1.y += acc[tm][tn][3];
                *(float2*)(o0 + col) = e0;
                *(float2*)(o1 + col) = e1;
            }
        }
    }
}

// =============================================================================
// Matrix power kernels (1 row per block — the faster configuration).
// =============================================================================
__global__ __launch_bounds__(256) void w2_kernel(const float* __restrict__ W)
{
    __shared__ float rowj[256];
    const int j = blockIdx.x, k = threadIdx.x;
    rowj[k] = W[(size_t)j * 512 + 256 + k];
    __syncthreads();
    float acc = 0.f;
    #pragma unroll 8
    for (int m = 0; m < 256; m++)
        acc += rowj[m] * W[(size_t)m * 512 + 256 + k];
    g_W2[j * 256 + k] = acc;
}

__global__ __launch_bounds__(256) void wsq_kernel(int which)
{
    const float* src = (which == 0) ? g_W2 : (which == 1) ? g_W4 : g_W8;
    float*       dst = (which == 0) ? g_W4 : (which == 1) ? g_W8 : g_W16;
    __shared__ float rowj[256];
    const int j = blockIdx.x, k = threadIdx.x;
    rowj[k] = src[j * 256 + k];
    __syncthreads();
    float acc = 0.f;
    #pragma unroll 8
    for (int m = 0; m < 256; m++)
        acc += rowj[m] * src[m * 256 + k];
    dst[j * 256 + k] = acc;
}

// bf16 hi/lo pre-split of the 5 GEMM B matrices (Wx, Wh, W2, W4, W8)
__global__ __launch_bounds__(128) void bsplit_kernel(const float* __restrict__ W)
{
    const int m = blockIdx.y, j = blockIdx.x, t = threadIdx.x;
    float x0, x1;
    if (m == 0)      { x0 = W[(size_t)j * 512 + 2 * t];       x1 = W[(size_t)j * 512 + 2 * t + 1]; }
    else if (m == 1) { x0 = W[(size_t)j * 512 + 256 + 2 * t]; x1 = W[(size_t)j * 512 + 257 + 2 * t]; }
    else {
        const float* S = (m == 2) ? g_W2 : (m == 3) ? g_W4 : g_W8;
        x0 = S[j * 256 + 2 * t]; x1 = S[j * 256 + 2 * t + 1];
    }
    uint32_t hi = packbf(x0, x1);
    float r0 = x0 - __uint_as_float(hi << 16);
    float r1 = x1 - __uint_as_float(hi & 0xffff0000u);
    uint32_t lo = packbf(r0, r1);
    g_Bh16[m * 32768 + j * 128 + t] = hi;
    g_Bl16[m * 32768 + j * 128 + t] = lo;
}

// =============================================================================
// Phase 2: W^16 scan, 128 steps (unchanged — proven fp32 FFMA2 path).
// =============================================================================
__global__ __launch_bounds__(512, 1) void rnn_scan(
    const float* __restrict__ hidden, float* __restrict__ out)
{
    extern __shared__ u64 dynsm[];
    u64*   resw = dynsm;                     // [20][512] u64         (81920 B)
    float* part = (float*)(dynsm + 10240);   // [256*9] floats         (9216 B)
    u64*   h2   = dynsm + 11392;             // [2][8*17] u64 (padded) (2176 B)

    const int tid  = threadIdx.x;
    const int b    = blockIdx.x;
    const int q    = tid & 7;
    const int jset = tid >> 3;

    u64 w[4][11];
    #pragma unroll
    for (int u = 0; u < 4; u++) {
        const u64* wr = (const u64*)(g_W16 + (size_t)(jset * 4 + u) * 256);
        #pragma unroll
        for (int i = 0; i < 11; i++) w[u][i] = wr[q * 16 + i];
        #pragma unroll
        for (int ir = 0; ir < 5; ir++)
            resw[(u * 5 + ir) * 512 + tid] = wr[q * 16 + 11 + ir];
    }

    if (tid < 128) {
        u64 hv = ((const u64*)(hidden + (size_t)b * 256))[tid];
        h2[(tid >> 4) * 17 + (tid & 15)] = hv;
    }

    float xpre = 0.f;
    float* outp = out + (size_t)b * 2048 * 256 + 15 * 256 + tid;
    if (tid < 256) xpre = *outp;

    __syncthreads();

    const u64* rw = resw + tid;

    #pragma unroll 1
    for (int t = 0; t < 128; t++) {
        const u64* hb = h2 + (t & 1) * 136 + q * 17;
        u64 a0 = 0, a1 = 0, a2 = 0, a3 = 0;
        #pragma unroll
        for (int i = 0; i < 11; i++) {
            u64 hh = hb[i];
            a0 = ffma2(w[0][i], hh, a0);
            a1 = ffma2(w[1][i], hh, a1);
            a2 = ffma2(w[2][i], hh, a2);
            a3 = ffma2(w[3][i], hh, a3);
        }
        #pragma unroll
        for (int ir = 0; ir < 5; ir++) {
            u64 hh = hb[11 + ir];
            a0 = ffma2(rw[(0 * 5 + ir) * 512], hh, a0);
            a1 = ffma2(rw[(1 * 5 + ir) * 512], hh, a1);
            a2 = ffma2(rw[(2 * 5 + ir) * 512], hh, a2);
            a3 = ffma2(rw[(3 * 5 + ir) * 512], hh, a3);
        }
        float2 f0 = unpack2(a0), f1 = unpack2(a1), f2 = unpack2(a2), f3 = unpack2(a3);
        const int pb = (jset * 4) * 9 + q;
        part[pb]      = f0.x + f0.y;
        part[pb + 9]  = f1.x + f1.y;
        part[pb + 18] = f2.x + f2.y;
        part[pb + 27] = f3.x + f3.y;
        __syncthreads();
        if (tid < 256) {
            const float* pr = part + tid * 9;
            float s = ((pr[0] + pr[1]) + (pr[2] + pr[3]))
                    + ((pr[4] + pr[5]) + (pr[6] + pr[7]));
            float hnew = s + xpre;
            int p = tid >> 1;
            float* hw = (float*)(h2 + ((t + 1) & 1) * 136);
            hw[((p >> 4) * 17 + (p & 15)) * 2 + (tid & 1)] = hnew;
            *outp = hnew;
            if (t < 127) xpre = outp[4096];
            outp += 4096;
        }
        __syncthreads();
    }
}

// =============================================================================
extern "C" void kernel_launch(void* const* d_in, const int* in_sizes, int n_in,
                              void* d_out, int out_size)
{
    (void)in_sizes; (void)n_in; (void)out_size;
    const float* X      = (const float*)d_in[0];   // input_seq [64,2048,256]
    const float* hidden = (const float*)d_in[1];   // [64,256]
    const float* W      = (const float*)d_in[2];   // [256,512]
    const float* bias   = (const float*)d_in[3];   // [256]
    float* out          = (float*)d_out;           // [64,2048,256]

    cudaFuncSetAttribute(mma_gemm,
        cudaFuncAttributeMaxDynamicSharedMemorySize, MMA_SMEM_BYTES);
    cudaFuncSetAttribute(rnn_scan,
        cudaFuncAttributeMaxDynamicSharedMemorySize, 93312);

    // 1) Wh powers: W2, W4, W8, W16; then bf16 pre-split of B matrices.
    w2_kernel<<<256, 256>>>(W);
    wsq_kernel<<<256, 256>>>(0);
    wsq_kernel<<<256, 256>>>(1);
    wsq_kernel<<<256, 256>>>(2);
    bsplit_kernel<<<dim3(256, 5), 128>>>(W);

    // 2) xproj (tensor cores): out = X @ Wx^T + bias.
    mma_gemm<<<dim3(1024, 2), 256, MMA_SMEM_BYTES>>>(X, hidden, W, bias, out, 0, 0);

    // 3) correction tree, levels 1..4 (B = Wh, W2, W4, W8).
    mma_gemm<<<dim3(512, 2), 256, MMA_SMEM_BYTES>>>(X, hidden, W, bias, out, 1, 1);
    mma_gemm<<<dim3(256, 2), 256, MMA_SMEM_BYTES>>>(X, hidden, W, bias, out, 1, 2);
    mma_gemm<<<dim3(128, 2), 256, MMA_SMEM_BYTES>>>(X, hidden, W, bias, out, 1, 3);
    mma_gemm<<<dim3(64,  2), 256, MMA_SMEM_BYTES>>>(X, hidden, W, bias, out, 1, 4);

    // 4) W^16 scan, 128 steps.
    rnn_scan<<<64, 512, 93312>>>(hidden, out);

    // 5) backfill levels 3..0 (B = W8, W4, W2, Wh).
    mma_gemm<<<dim3(64,  2), 256, MMA_SMEM_BYTES>>>(X, hidden, W, bias, out, 2, 3);
    mma_gemm<<<dim3(128, 2), 256, MMA_SMEM_BYTES>>>(X, hidden, W, bias, out, 2, 2);
    mma_gemm<<<dim3(256, 2), 256, MMA_SMEM_BYTES>>>(X, hidden, W, bias, out, 2, 1);
    mma_gemm<<<dim3(512, 2), 256, MMA_SMEM_BYTES>>>(X, hidden, W, bias, out, 2, 0);
}